// round 2
// baseline (speedup 1.0000x reference)
#include <cuda_runtime.h>
#include <math.h>

#define BATCH 32
#define NSEGC 8
#define SLEN  128
#define TTOT  1024
#define KTAG  16
#define MROWS 32768

// ---------------- device scratch ----------------
__device__ float g_X1 [(size_t)MROWS * 256];
__device__ float g_G1 [(size_t)MROWS * 1024];
__device__ float g_OUT1[(size_t)MROWS * 256];
__device__ float g_P2 [(size_t)MROWS * 256];
__device__ float g_G2 [(size_t)MROWS * 1024];
__device__ float g_OUT2[(size_t)MROWS * 256];
__device__ float g_EM [(size_t)MROWS * KTAG];
__device__ float g_Hf[2][BATCH][128];
__device__ float g_Cf[2][BATCH][128];
__device__ uint4 g_HIST4[(size_t)(TTOT - 1) * BATCH];   // 16 bytes per (t,b): backptr per tag

// ---------------- embedding gather ----------------
__global__ void k_embed(const int* __restrict__ texts, const float* __restrict__ emb)
{
    int r    = blockIdx.x * 4 + (threadIdx.x >> 6);
    int lane = threadIdx.x & 63;
    int tok  = texts[r];
    const float4* src = (const float4*)(emb + (size_t)tok * 256);
    float4*       dst = (float4*)(g_X1 + (size_t)r * 256);
    dst[lane] = src[lane];
}

// ---------------- fp32 SIMT GEMM: C[M][1024] = A[M][256] @ [Wf|Wb]^T + (b1+b2) ----------------
__global__ __launch_bounds__(256) void k_gemm(
    const float* __restrict__ A,
    const float* __restrict__ Wf, const float* __restrict__ Wb,
    const float* __restrict__ b1f, const float* __restrict__ b2f,
    const float* __restrict__ b1b, const float* __restrict__ b2b,
    float* __restrict__ C, const int* __restrict__ lengths, int skipmode)
{
    int bm = blockIdx.x * 128;
    int bn = blockIdx.y * 128;
    if (skipmode) {                 // stage2: skip row-tiles entirely past new_len[b]
        int b = bm >> 10;
        int nl = 0;
#pragma unroll
        for (int s = 0; s < 8; s++) nl += lengths[b * 8 + s];
        if ((bm & 1023) >= nl) return;
    }
    const float *W, *bb1, *bb2; int nbase;
    if (bn < 512) { W = Wf; bb1 = b1f; bb2 = b2f; nbase = bn; }
    else          { W = Wb; bb1 = b1b; bb2 = b2b; nbase = bn - 512; }

    __shared__ float As[16][132];
    __shared__ float Bs[16][132];
    int tid = threadIdx.x;
    int tm = (tid >> 4) << 3, tn = (tid & 15) << 3;
    int lr = tid >> 1, lk = (tid & 1) << 3;
    const float* Ar = A + (size_t)(bm + lr) * 256 + lk;
    const float* Wr = W + (size_t)(nbase + lr) * 256 + lk;

    float acc[8][8];
#pragma unroll
    for (int i = 0; i < 8; i++)
#pragma unroll
        for (int j = 0; j < 8; j++) acc[i][j] = 0.0f;

    for (int k0 = 0; k0 < 256; k0 += 16) {
        float4 a0 = *(const float4*)(Ar + k0);
        float4 a1 = *(const float4*)(Ar + k0 + 4);
        float4 w0 = *(const float4*)(Wr + k0);
        float4 w1 = *(const float4*)(Wr + k0 + 4);
        __syncthreads();
        As[lk+0][lr]=a0.x; As[lk+1][lr]=a0.y; As[lk+2][lr]=a0.z; As[lk+3][lr]=a0.w;
        As[lk+4][lr]=a1.x; As[lk+5][lr]=a1.y; As[lk+6][lr]=a1.z; As[lk+7][lr]=a1.w;
        Bs[lk+0][lr]=w0.x; Bs[lk+1][lr]=w0.y; Bs[lk+2][lr]=w0.z; Bs[lk+3][lr]=w0.w;
        Bs[lk+4][lr]=w1.x; Bs[lk+5][lr]=w1.y; Bs[lk+6][lr]=w1.z; Bs[lk+7][lr]=w1.w;
        __syncthreads();
#pragma unroll
        for (int kk = 0; kk < 16; kk++) {
            float ar[8], br[8];
            float4 t0 = *(const float4*)&As[kk][tm];
            float4 t1 = *(const float4*)&As[kk][tm + 4];
            ar[0]=t0.x; ar[1]=t0.y; ar[2]=t0.z; ar[3]=t0.w;
            ar[4]=t1.x; ar[5]=t1.y; ar[6]=t1.z; ar[7]=t1.w;
            float4 u0 = *(const float4*)&Bs[kk][tn];
            float4 u1 = *(const float4*)&Bs[kk][tn + 4];
            br[0]=u0.x; br[1]=u0.y; br[2]=u0.z; br[3]=u0.w;
            br[4]=u1.x; br[5]=u1.y; br[6]=u1.z; br[7]=u1.w;
#pragma unroll
            for (int i = 0; i < 8; i++)
#pragma unroll
                for (int j = 0; j < 8; j++)
                    acc[i][j] = fmaf(ar[i], br[j], acc[i][j]);
        }
    }
#pragma unroll
    for (int i = 0; i < 8; i++) {
        float* Crow = C + (size_t)(bm + tm + i) * 1024 + bn + tn;
#pragma unroll
        for (int j = 0; j < 8; j++) {
            int nidx = nbase + tn + j;
            Crow[j] = acc[i][j] + bb1[nidx] + bb2[nidx];
        }
    }
}

// ---------------- LSTM recurrent core ----------------
#define SMEM_LSTM ((512 * 68 + 128 + 512) * 4)

__device__ __forceinline__ void lstm_run(
    const float* __restrict__ Whh, const float* __restrict__ Gbase,
    float* __restrict__ Obase, int len, int dir, int t,
    float* ws, float* hs, float* ga,
    float h_init, float c_init, int write_final, int b)
{
    const float* wr = Whh + t * 128;
    float w[64];
#pragma unroll
    for (int q = 0; q < 16; q++) {
        float4 v = *(const float4*)(wr + q * 4);
        w[4*q]=v.x; w[4*q+1]=v.y; w[4*q+2]=v.z; w[4*q+3]=v.w;
    }
    float* wsr = ws + t * 68;
#pragma unroll
    for (int q = 0; q < 16; q++)
        *(float4*)(wsr + 4 * q) = *(const float4*)(wr + 64 + 4 * q);

    float c = c_init;
    if (t < 128) hs[t] = h_init;
    __syncthreads();

    int s    = dir ? (len - 1) : 0;
    int step = dir ? -1 : 1;
    float xg = Gbase[(size_t)s * 1024];
    for (int it = 0; it < len; it++) {
        int s_next = s + step;
        float xg_next = (it + 1 < len) ? Gbase[(size_t)s_next * 1024] : 0.0f;
        float acc = xg;
        const float4* h4 = (const float4*)hs;
#pragma unroll
        for (int q = 0; q < 16; q++) {
            float4 hv = h4[q];
            acc = fmaf(w[4*q  ], hv.x, acc);
            acc = fmaf(w[4*q+1], hv.y, acc);
            acc = fmaf(w[4*q+2], hv.z, acc);
            acc = fmaf(w[4*q+3], hv.w, acc);
        }
#pragma unroll
        for (int q = 0; q < 16; q++) {
            float4 wv = *(const float4*)(wsr + 4 * q);
            float4 hv = h4[16 + q];
            acc = fmaf(wv.x, hv.x, acc);
            acc = fmaf(wv.y, hv.y, acc);
            acc = fmaf(wv.z, hv.z, acc);
            acc = fmaf(wv.w, hv.w, acc);
        }
        float act;
        if ((t >> 7) == 2) act = tanhf(acc);                 // g-gate rows
        else               act = 1.0f / (1.0f + expf(-acc)); // i,f,o
        ga[t] = act;
        __syncthreads();
        if (t < 128) {
            float iv = ga[t], fv = ga[128 + t], gv = ga[256 + t], ov = ga[384 + t];
            c = fmaf(fv, c, iv * gv);
            float hn = ov * tanhf(c);
            hs[t] = hn;
            Obase[(size_t)s * 256 + t] = hn;
        }
        __syncthreads();
        xg = xg_next;
        s  = s_next;
    }
    if (write_final && t < 128) {
        g_Hf[dir][b][t] = hs[t];
        g_Cf[dir][b][t] = c;
    }
}

__global__ __launch_bounds__(512, 1) void k_lstm1(
    const int* __restrict__ lengths,
    const float* __restrict__ Whh_f, const float* __restrict__ Whh_b)
{
    extern __shared__ float sm[];
    float* ws = sm;
    float* hs = sm + 512 * 68;
    float* ga = hs + 128;
    int t   = threadIdx.x;
    int blk = blockIdx.x;
    int dir = blk >> 8;
    int b   = (blk & 255) >> 3;
    int seg = blk & 7;
    int len = lengths[b * NSEGC + seg];
    const float* Gbase = g_G1 + (size_t)((b * NSEGC + seg) * SLEN) * 1024 + dir * 512 + t;
    float* Obase = g_OUT1 + (size_t)((b * NSEGC + seg) * SLEN) * 256 + dir * 128;
    lstm_run(dir ? Whh_b : Whh_f, Gbase, Obase, len, dir, t, ws, hs, ga,
             0.0f, 0.0f, (seg == NSEGC - 1), b);
}

__global__ __launch_bounds__(512, 1) void k_lstm2(
    const int* __restrict__ lengths,
    const float* __restrict__ Whh_f, const float* __restrict__ Whh_b)
{
    extern __shared__ float sm[];
    float* ws = sm;
    float* hs = sm + 512 * 68;
    float* ga = hs + 128;
    int t   = threadIdx.x;
    int blk = blockIdx.x;
    int dir = blk >> 5;
    int b   = blk & 31;
    int len = 0;
#pragma unroll
    for (int s = 0; s < 8; s++) len += lengths[b * 8 + s];
    float hi = (t < 128) ? g_Hf[dir][b][t & 127] : 0.0f;
    float ci = (t < 128) ? g_Cf[dir][b][t & 127] : 0.0f;
    const float* Gbase = g_G2 + (size_t)(b * 1024) * 1024 + dir * 512 + t;
    float* Obase = g_OUT2 + (size_t)(b * 1024) * 256 + dir * 128;
    lstm_run(dir ? Whh_b : Whh_f, Gbase, Obase, len, dir, t, ws, hs, ga,
             hi, ci, 0, b);
}

// ---------------- pack valid stage-1 rows into stage-2 input ----------------
__global__ void k_pack(const int* __restrict__ lengths)
{
    int blk = blockIdx.x;
    int b = blk >> 3, seg = blk & 7;
    int off = 0;
    for (int s = 0; s < seg; s++) off += lengths[b * 8 + s];
    int len = lengths[b * 8 + seg];
    const float4* src = (const float4*)(g_OUT1 + (size_t)((b * 8 + seg) * 128) * 256);
    float4*       dst = (float4*)(g_P2 + (size_t)(b * 1024 + off) * 256);
    int n4 = len * 64;
    for (int i = threadIdx.x; i < n4; i += blockDim.x) dst[i] = src[i];
}

// ---------------- emission = OUT2 @ Wlin^T + blin ----------------
__global__ void k_emission(const float* __restrict__ Wlin, const float* __restrict__ blin,
                           const int* __restrict__ lengths)
{
    int b = blockIdx.x;
    int L = 0;
#pragma unroll
    for (int s = 0; s < 8; s++) L += lengths[b * 8 + s];
    for (int idx = threadIdx.x; idx < L * 16; idx += blockDim.x) {
        int t = idx >> 4, k = idx & 15;
        const float4* xr = (const float4*)(g_OUT2 + (size_t)(b * 1024 + t) * 256);
        const float4* wr = (const float4*)(Wlin + k * 256);
        float a0 = 0.f;
#pragma unroll
        for (int q = 0; q < 64; q++) {
            float4 x = xr[q], w = wr[q];
            a0 = fmaf(x.x, w.x, a0); a0 = fmaf(x.y, w.y, a0);
            a0 = fmaf(x.z, w.z, a0); a0 = fmaf(x.w, w.w, a0);
        }
        g_EM[(size_t)(b * 1024 + t) * 16 + k] = a0 + blin[k];
    }
}

// ---------------- Viterbi: warp per batch, K=16 in lanes ----------------
__global__ __launch_bounds__(1024, 1) void k_viterbi(
    const float* __restrict__ startv, const float* __restrict__ trans,
    const float* __restrict__ endv, const int* __restrict__ lengths,
    float* __restrict__ out)
{
    int tid  = threadIdx.x;
    int b    = tid >> 5;
    int lane = tid & 31;
    int j    = lane & 15;
    int L = 0;
#pragma unroll
    for (int s = 0; s < 8; s++) L += lengths[b * 8 + s];
    float trC[16];
#pragma unroll
    for (int i = 0; i < 16; i++) trC[i] = trans[i * 16 + j];
    const float* em = g_EM + ((size_t)b << 10) * 16;

    float sc  = startv[j] + em[j];          // t = 0
    float emj = em[16 + j];                  // t = 1 (L >= 8 always)
    unsigned char* hist = (unsigned char*)g_HIST4;
    for (int t = 1; t < L; t++) {
        float em_next = (t + 1 < L) ? em[(t + 1) * 16 + j] : 0.0f;
        float best = -3.4e38f; int bi = 0;
#pragma unroll
        for (int i = 0; i < 16; i++) {
            float v = (__shfl_sync(0xFFFFFFFFu, sc, i) + trC[i]) + emj;
            if (v > best) { best = v; bi = i; }
        }
        sc = best;
        if (lane < 16)
            hist[((size_t)(t - 1) * 32 + b) * 16 + j] = (unsigned char)bi;
        emj = em_next;
    }
    float fin = sc + endv[j];
    float bestv = -3.4e38f; int last = 0;
#pragma unroll
    for (int i = 0; i < 16; i++) {
        float v = __shfl_sync(0xFFFFFFFFu, fin, i);
        if (v > bestv) { bestv = v; last = i; }
    }
    if (lane == 0) {
        out[32768 + b] = bestv;
        int cur = last;
        out[(TTOT - 1) * 32 + b] = (float)cur;
#pragma unroll 4
        for (int t = TTOT - 1; t >= 1; t--) {
            uint4 hrow = g_HIST4[(size_t)(t - 1) * 32 + b];
            if (t < L) {
                unsigned wv = ((const unsigned*)&hrow)[cur >> 2];
                cur = (int)((wv >> ((cur & 3) * 8)) & 0xFFu);
            }
            out[(t - 1) * 32 + b] = (float)cur;
        }
    }
}

// ---------------- launch ----------------
extern "C" void kernel_launch(void* const* d_in, const int* in_sizes, int n_in,
                              void* d_out, int out_size)
{
    const int*   texts   = (const int*)  d_in[0];
    const int*   lengths = (const int*)  d_in[1];
    const float* emb     = (const float*)d_in[2];
    const float* Wih_f   = (const float*)d_in[3];
    const float* Whh_f   = (const float*)d_in[4];
    const float* bih_f   = (const float*)d_in[5];
    const float* bhh_f   = (const float*)d_in[6];
    const float* Wih_b   = (const float*)d_in[7];
    const float* Whh_b   = (const float*)d_in[8];
    const float* bih_b   = (const float*)d_in[9];
    const float* bhh_b   = (const float*)d_in[10];
    const float* Wlin    = (const float*)d_in[11];
    const float* blin    = (const float*)d_in[12];
    const float* crf_s   = (const float*)d_in[13];
    const float* crf_t   = (const float*)d_in[14];
    const float* crf_e   = (const float*)d_in[15];
    float* out = (float*)d_out;

    cudaFuncSetAttribute(k_lstm1, cudaFuncAttributeMaxDynamicSharedMemorySize, SMEM_LSTM);
    cudaFuncSetAttribute(k_lstm2, cudaFuncAttributeMaxDynamicSharedMemorySize, SMEM_LSTM);

    float *pX1, *pG1, *pP2, *pG2;
    cudaGetSymbolAddress((void**)&pX1, g_X1);
    cudaGetSymbolAddress((void**)&pG1, g_G1);
    cudaGetSymbolAddress((void**)&pP2, g_P2);
    cudaGetSymbolAddress((void**)&pG2, g_G2);

    k_embed<<<MROWS / 4, 256>>>(texts, emb);
    k_gemm<<<dim3(256, 8), 256>>>(pX1, Wih_f, Wih_b, bih_f, bhh_f, bih_b, bhh_b,
                                  pG1, lengths, 0);
    k_lstm1<<<512, 512, SMEM_LSTM>>>(lengths, Whh_f, Whh_b);
    k_pack<<<256, 256>>>(lengths);
    k_gemm<<<dim3(256, 8), 256>>>(pP2, Wih_f, Wih_b, bih_f, bhh_f, bih_b, bhh_b,
                                  pG2, lengths, 1);
    k_lstm2<<<64, 512, SMEM_LSTM>>>(lengths, Whh_f, Whh_b);
    k_emission<<<32, 256>>>(Wlin, blin, lengths);
    k_viterbi<<<1, 1024>>>(crf_s, crf_t, crf_e, lengths, out);
}

// round 3
// speedup vs baseline: 1.0735x; 1.0735x over previous
#include <cuda_runtime.h>
#include <mma.h>
#include <math.h>
using namespace nvcuda;

#define BATCH 32
#define NSEGC 8
#define SLEN  128
#define TTOT  1024
#define KTAG  16
#define MROWS 32768

// ---------------- device scratch ----------------
__device__ float g_G1 [(size_t)MROWS * 1024];   // stage1 x-gates (packed rows)
__device__ float g_P2 [(size_t)MROWS * 256];    // packed lstm2 input (= packed stage1 out)
__device__ float g_G2 [(size_t)MROWS * 1024];   // stage2 x-gates (packed rows)
__device__ float g_OUT2[(size_t)MROWS * 256];   // stage2 outputs (packed)
__device__ float g_EM [(size_t)MROWS * KTAG];   // emissions (packed)
__device__ int   g_segoff[257];                 // prefix sums of lengths; [256]=total
__device__ int   g_tokmap[MROWS];               // packed row -> token id
__device__ float g_Hf[2][BATCH][128];
__device__ float g_Cf[2][BATCH][128];
__device__ uint4 g_HIST4[(size_t)(TTOT - 1) * BATCH];

// ---------------- offsets ----------------
__global__ void k_offsets(const int* __restrict__ lengths)
{
    if (threadIdx.x == 0) {
        int acc = 0;
        for (int i = 0; i < 256; i++) { g_segoff[i] = acc; acc += lengths[i]; }
        g_segoff[256] = acc;
    }
}

__global__ void k_rowmap(const int* __restrict__ texts, const int* __restrict__ lengths)
{
    int bs = blockIdx.x;                 // (b,seg) flat
    int len = lengths[bs];
    int off = g_segoff[bs];
    int s = threadIdx.x;
    if (s < len) g_tokmap[off + s] = texts[bs * 128 + s];
}

// ---------------- 3xTF32 tensor-core GEMM ----------------
// C[packed_rows][1024] = A[rows][256] @ [Wf|Wb]^T + (b1+b2)
// GATHER=1: A row = emb[tokmap[row]]; GATHER=0: A row = A[row].
#define SMEM_G ((2 * 128 * 40 + 16 * 136) * 4)

template<int GATHER>
__global__ __launch_bounds__(256, 2) void k_gemm_tf32(
    const float* __restrict__ A,
    const float* __restrict__ Wf, const float* __restrict__ Wb,
    const float* __restrict__ b1f, const float* __restrict__ b2f,
    const float* __restrict__ b1b, const float* __restrict__ b2b,
    float* __restrict__ C)
{
    int total = g_segoff[256];
    int bm = blockIdx.x * 128;
    if (bm >= total) return;
    int bn = blockIdx.y * 128;
    const float *W, *bb1, *bb2; int nbase;
    if (bn < 512) { W = Wf; bb1 = b1f; bb2 = b2f; nbase = bn; }
    else          { W = Wb; bb1 = b1b; bb2 = b2b; nbase = bn - 512; }

    extern __shared__ float sm[];
    float* As     = sm;                   // [128][40]
    float* Bs     = sm + 128 * 40;        // [128][40]
    float* bias_s = sm + 2 * 128 * 40;    // [16][136]

    int tid = threadIdx.x;
    for (int i = tid; i < 16 * 128; i += 256) {
        int r = i >> 7, c = i & 127;
        bias_s[r * 136 + c] = bb1[nbase + c] + bb2[nbase + c];
    }

    int r0 = tid >> 3;
    int f4 = (tid & 7) * 4;
    const float* arow[4];
#pragma unroll
    for (int p = 0; p < 4; p++) {
        int pr = bm + r0 + 32 * p;
        if (GATHER) {
            int tok = (pr < total) ? g_tokmap[pr] : 0;
            arow[p] = A + (size_t)tok * 256;
        } else {
            arow[p] = A + (size_t)pr * 256;
        }
    }
    const float* wrow = W + (size_t)(nbase + r0) * 256;

    int wid = tid >> 5;
    int lm = (wid & 3) * 32;     // warp m offset (2 x m16)
    int ln = (wid >> 2) * 64;    // warp n offset (4 x n16)

    wmma::fragment<wmma::accumulator, 16, 16, 8, float> acc[2][4];
    __syncthreads();
#pragma unroll
    for (int mi = 0; mi < 2; mi++)
#pragma unroll
        for (int ni = 0; ni < 4; ni++)
            wmma::load_matrix_sync(acc[mi][ni], bias_s + ln + ni * 16, 136,
                                   wmma::mem_row_major);

    for (int k0 = 0; k0 < 256; k0 += 32) {
        float4 av[4], wv[4];
#pragma unroll
        for (int p = 0; p < 4; p++) {
            av[p] = *(const float4*)(arow[p] + k0 + f4);
            wv[p] = *(const float4*)(wrow + (size_t)p * 32 * 256 + k0 + f4);
        }
        __syncthreads();
#pragma unroll
        for (int p = 0; p < 4; p++) {
            *(float4*)&As[(r0 + 32 * p) * 40 + f4] = av[p];
            *(float4*)&Bs[(r0 + 32 * p) * 40 + f4] = wv[p];
        }
        __syncthreads();
#pragma unroll
        for (int ks = 0; ks < 4; ks++) {
            wmma::fragment<wmma::matrix_a, 16, 16, 8, wmma::precision::tf32,
                           wmma::row_major> ah[2], al[2];
#pragma unroll
            for (int mi = 0; mi < 2; mi++) {
                wmma::load_matrix_sync(ah[mi], As + (lm + mi * 16) * 40 + ks * 8, 40);
#pragma unroll
                for (int e = 0; e < ah[mi].num_elements; e++) {
                    float v = ah[mi].x[e];
                    float hi = wmma::__float_to_tf32(v);
                    ah[mi].x[e] = hi;
                    al[mi].x[e] = wmma::__float_to_tf32(v - hi);
                }
            }
#pragma unroll
            for (int ni = 0; ni < 4; ni++) {
                wmma::fragment<wmma::matrix_b, 16, 16, 8, wmma::precision::tf32,
                               wmma::col_major> bh, bl;
                wmma::load_matrix_sync(bh, Bs + (ln + ni * 16) * 40 + ks * 8, 40);
#pragma unroll
                for (int e = 0; e < bh.num_elements; e++) {
                    float v = bh.x[e];
                    float hi = wmma::__float_to_tf32(v);
                    bh.x[e] = hi;
                    bl.x[e] = wmma::__float_to_tf32(v - hi);
                }
#pragma unroll
                for (int mi = 0; mi < 2; mi++) {
                    wmma::mma_sync(acc[mi][ni], ah[mi], bl, acc[mi][ni]);
                    wmma::mma_sync(acc[mi][ni], al[mi], bh, acc[mi][ni]);
                    wmma::mma_sync(acc[mi][ni], ah[mi], bh, acc[mi][ni]);
                }
            }
        }
    }
#pragma unroll
    for (int mi = 0; mi < 2; mi++)
#pragma unroll
        for (int ni = 0; ni < 4; ni++)
            wmma::store_matrix_sync(
                C + (size_t)(bm + lm + mi * 16) * 1024 + bn + ln + ni * 16,
                acc[mi][ni], 1024, wmma::mem_row_major);
}

// ---------------- LSTM recurrent core ----------------
#define SMEM_LSTM ((512 * 68 + 128 + 512) * 4)

__device__ __forceinline__ void lstm_run(
    const float* __restrict__ Whh, const float* __restrict__ Gbase,
    float* __restrict__ Obase, int len, int dir, int t,
    float* ws, float* hs, float* ga,
    float h_init, float c_init, int write_final, int b)
{
    const float* wr = Whh + t * 128;
    float w[64];
#pragma unroll
    for (int q = 0; q < 16; q++) {
        float4 v = *(const float4*)(wr + q * 4);
        w[4*q]=v.x; w[4*q+1]=v.y; w[4*q+2]=v.z; w[4*q+3]=v.w;
    }
    float* wsr = ws + t * 68;
#pragma unroll
    for (int q = 0; q < 16; q++)
        *(float4*)(wsr + 4 * q) = *(const float4*)(wr + 64 + 4 * q);

    float c = c_init;
    if (t < 128) hs[t] = h_init;
    __syncthreads();

    int s    = dir ? (len - 1) : 0;
    int step = dir ? -1 : 1;
    float xg = Gbase[(size_t)s * 1024];
    for (int it = 0; it < len; it++) {
        int s_next = s + step;
        float xg_next = (it + 1 < len) ? Gbase[(size_t)s_next * 1024] : 0.0f;
        float acc = xg;
        const float4* h4 = (const float4*)hs;
#pragma unroll
        for (int q = 0; q < 16; q++) {
            float4 hv = h4[q];
            acc = fmaf(w[4*q  ], hv.x, acc);
            acc = fmaf(w[4*q+1], hv.y, acc);
            acc = fmaf(w[4*q+2], hv.z, acc);
            acc = fmaf(w[4*q+3], hv.w, acc);
        }
#pragma unroll
        for (int q = 0; q < 16; q++) {
            float4 wv = *(const float4*)(wsr + 4 * q);
            float4 hv = h4[16 + q];
            acc = fmaf(wv.x, hv.x, acc);
            acc = fmaf(wv.y, hv.y, acc);
            acc = fmaf(wv.z, hv.z, acc);
            acc = fmaf(wv.w, hv.w, acc);
        }
        float act;
        if ((t >> 7) == 2) act = tanhf(acc);
        else               act = 1.0f / (1.0f + expf(-acc));
        ga[t] = act;
        __syncthreads();
        if (t < 128) {
            float iv = ga[t], fv = ga[128 + t], gv = ga[256 + t], ov = ga[384 + t];
            c = fmaf(fv, c, iv * gv);
            float hn = ov * tanhf(c);
            hs[t] = hn;
            Obase[(size_t)s * 256 + t] = hn;
        }
        __syncthreads();
        xg = xg_next;
        s  = s_next;
    }
    if (write_final && t < 128) {
        g_Hf[dir][b][t] = hs[t];
        g_Cf[dir][b][t] = c;
    }
}

__global__ __launch_bounds__(512, 1) void k_lstm1(
    const int* __restrict__ lengths,
    const float* __restrict__ Whh_f, const float* __restrict__ Whh_b)
{
    extern __shared__ float sm[];
    float* ws = sm;
    float* hs = sm + 512 * 68;
    float* ga = hs + 128;
    int t   = threadIdx.x;
    int blk = blockIdx.x;
    int dir = blk >> 8;
    int b   = (blk & 255) >> 3;
    int seg = blk & 7;
    int bs  = b * NSEGC + seg;
    int len = lengths[bs];
    int off = g_segoff[bs];
    const float* Gbase = g_G1 + (size_t)off * 1024 + dir * 512 + t;
    float* Obase = g_P2 + (size_t)off * 256 + dir * 128;   // write packed directly
    lstm_run(dir ? Whh_b : Whh_f, Gbase, Obase, len, dir, t, ws, hs, ga,
             0.0f, 0.0f, (seg == NSEGC - 1), b);
}

__global__ __launch_bounds__(512, 1) void k_lstm2(
    const int* __restrict__ lengths,
    const float* __restrict__ Whh_f, const float* __restrict__ Whh_b)
{
    extern __shared__ float sm[];
    float* ws = sm;
    float* hs = sm + 512 * 68;
    float* ga = hs + 128;
    int t   = threadIdx.x;
    int blk = blockIdx.x;
    int dir = blk >> 5;
    int b   = blk & 31;
    int base = g_segoff[b * 8];
    int len  = g_segoff[b * 8 + 8] - base;
    float hi = (t < 128) ? g_Hf[dir][b][t & 127] : 0.0f;
    float ci = (t < 128) ? g_Cf[dir][b][t & 127] : 0.0f;
    const float* Gbase = g_G2 + (size_t)base * 1024 + dir * 512 + t;
    float* Obase = g_OUT2 + (size_t)base * 256 + dir * 128;
    lstm_run(dir ? Whh_b : Whh_f, Gbase, Obase, len, dir, t, ws, hs, ga,
             hi, ci, 0, b);
}

// ---------------- emission = OUT2 @ Wlin^T + blin (packed) ----------------
__global__ void k_emission(const float* __restrict__ Wlin, const float* __restrict__ blin)
{
    int b = blockIdx.x;
    int base = g_segoff[b * 8];
    int L    = g_segoff[b * 8 + 8] - base;
    for (int idx = threadIdx.x; idx < L * 16; idx += blockDim.x) {
        int t = idx >> 4, k = idx & 15;
        const float4* xr = (const float4*)(g_OUT2 + (size_t)(base + t) * 256);
        const float4* wr = (const float4*)(Wlin + k * 256);
        float a0 = 0.f;
#pragma unroll
        for (int q = 0; q < 64; q++) {
            float4 x = xr[q], w = wr[q];
            a0 = fmaf(x.x, w.x, a0); a0 = fmaf(x.y, w.y, a0);
            a0 = fmaf(x.z, w.z, a0); a0 = fmaf(x.w, w.w, a0);
        }
        g_EM[(size_t)(base + t) * 16 + k] = a0 + blin[k];
    }
}

// ---------------- Viterbi: warp per batch, K=16 in lanes ----------------
__global__ __launch_bounds__(1024, 1) void k_viterbi(
    const float* __restrict__ startv, const float* __restrict__ trans,
    const float* __restrict__ endv, float* __restrict__ out)
{
    int tid  = threadIdx.x;
    int b    = tid >> 5;
    int lane = tid & 31;
    int j    = lane & 15;
    int base = g_segoff[b * 8];
    int L    = g_segoff[b * 8 + 8] - base;
    float trC[16];
#pragma unroll
    for (int i = 0; i < 16; i++) trC[i] = trans[i * 16 + j];
    const float* em = g_EM + (size_t)base * 16;

    float sc  = startv[j] + em[j];
    float emj = em[16 + j];
    unsigned char* hist = (unsigned char*)g_HIST4;
    for (int t = 1; t < L; t++) {
        float em_next = (t + 1 < L) ? em[(t + 1) * 16 + j] : 0.0f;
        float best = -3.4e38f; int bi = 0;
#pragma unroll
        for (int i = 0; i < 16; i++) {
            float v = (__shfl_sync(0xFFFFFFFFu, sc, i) + trC[i]) + emj;
            if (v > best) { best = v; bi = i; }
        }
        sc = best;
        if (lane < 16)
            hist[((size_t)(t - 1) * 32 + b) * 16 + j] = (unsigned char)bi;
        emj = em_next;
    }
    float fin = sc + endv[j];
    float bestv = -3.4e38f; int last = 0;
#pragma unroll
    for (int i = 0; i < 16; i++) {
        float v = __shfl_sync(0xFFFFFFFFu, fin, i);
        if (v > bestv) { bestv = v; last = i; }
    }
    if (lane == 0) {
        out[32768 + b] = bestv;
        int cur = last;
        out[(TTOT - 1) * 32 + b] = (float)cur;
#pragma unroll 4
        for (int t = TTOT - 1; t >= 1; t--) {
            uint4 hrow = g_HIST4[(size_t)(t - 1) * 32 + b];
            if (t < L) {
                unsigned wv = ((const unsigned*)&hrow)[cur >> 2];
                cur = (int)((wv >> ((cur & 3) * 8)) & 0xFFu);
            }
            out[(t - 1) * 32 + b] = (float)cur;
        }
    }
}

// ---------------- launch ----------------
extern "C" void kernel_launch(void* const* d_in, const int* in_sizes, int n_in,
                              void* d_out, int out_size)
{
    const int*   texts   = (const int*)  d_in[0];
    const int*   lengths = (const int*)  d_in[1];
    const float* emb     = (const float*)d_in[2];
    const float* Wih_f   = (const float*)d_in[3];
    const float* Whh_f   = (const float*)d_in[4];
    const float* bih_f   = (const float*)d_in[5];
    const float* bhh_f   = (const float*)d_in[6];
    const float* Wih_b   = (const float*)d_in[7];
    const float* Whh_b   = (const float*)d_in[8];
    const float* bih_b   = (const float*)d_in[9];
    const float* bhh_b   = (const float*)d_in[10];
    const float* Wlin    = (const float*)d_in[11];
    const float* blin    = (const float*)d_in[12];
    const float* crf_s   = (const float*)d_in[13];
    const float* crf_t   = (const float*)d_in[14];
    const float* crf_e   = (const float*)d_in[15];
    float* out = (float*)d_out;

    cudaFuncSetAttribute(k_lstm1, cudaFuncAttributeMaxDynamicSharedMemorySize, SMEM_LSTM);
    cudaFuncSetAttribute(k_lstm2, cudaFuncAttributeMaxDynamicSharedMemorySize, SMEM_LSTM);
    cudaFuncSetAttribute(k_gemm_tf32<1>, cudaFuncAttributeMaxDynamicSharedMemorySize, SMEM_G);
    cudaFuncSetAttribute(k_gemm_tf32<0>, cudaFuncAttributeMaxDynamicSharedMemorySize, SMEM_G);

    float *pG1, *pP2, *pG2;
    cudaGetSymbolAddress((void**)&pG1, g_G1);
    cudaGetSymbolAddress((void**)&pP2, g_P2);
    cudaGetSymbolAddress((void**)&pG2, g_G2);

    k_offsets<<<1, 32>>>(lengths);
    k_rowmap<<<256, 128>>>(texts, lengths);
    k_gemm_tf32<1><<<dim3(256, 8), 256, SMEM_G>>>(emb, Wih_f, Wih_b,
                                                  bih_f, bhh_f, bih_b, bhh_b, pG1);
    k_lstm1<<<512, 512, SMEM_LSTM>>>(lengths, Whh_f, Whh_b);
    k_gemm_tf32<0><<<dim3(256, 8), 256, SMEM_G>>>(pP2, Wih_f, Wih_b,
                                                  bih_f, bhh_f, bih_b, bhh_b, pG2);
    k_lstm2<<<64, 512, SMEM_LSTM>>>(lengths, Whh_f, Whh_b);
    k_emission<<<32, 256>>>(Wlin, blin);
    k_viterbi<<<1, 1024>>>(crf_s, crf_t, crf_e, out);
}

// round 4
// speedup vs baseline: 1.0752x; 1.0016x over previous
#include <cuda_runtime.h>
#include <mma.h>
#include <math.h>
using namespace nvcuda;

#define BATCH 32
#define NSEGC 8
#define SLEN  128
#define TTOT  1024
#define KTAG  16
#define MROWS 32768

// ---------------- device scratch ----------------
__device__ float g_G1 [(size_t)MROWS * 1024];   // stage1 x-gates (packed rows)
__device__ float g_P2 [(size_t)MROWS * 256];    // packed lstm2 input (= packed stage1 out)
__device__ float g_G2 [(size_t)MROWS * 1024];   // stage2 x-gates (packed rows)
__device__ float g_OUT2[(size_t)MROWS * 256];   // stage2 outputs (packed)
__device__ float g_EM [(size_t)MROWS * KTAG];   // emissions (packed)
__device__ int   g_segoff[257];                 // prefix sums of lengths; [256]=total
__device__ int   g_tokmap[MROWS];               // packed row -> token id
__device__ float g_Hf[2][BATCH][128];
__device__ float g_Cf[2][BATCH][128];
__device__ uint4 g_HIST4[(size_t)(TTOT - 1) * BATCH];

// ---------------- offsets ----------------
__global__ void k_offsets(const int* __restrict__ lengths)
{
    if (threadIdx.x == 0) {
        int acc = 0;
        for (int i = 0; i < 256; i++) { g_segoff[i] = acc; acc += lengths[i]; }
        g_segoff[256] = acc;
    }
}

__global__ void k_rowmap(const int* __restrict__ texts, const int* __restrict__ lengths)
{
    int bs = blockIdx.x;                 // (b,seg) flat
    int len = lengths[bs];
    int off = g_segoff[bs];
    int s = threadIdx.x;
    if (s < len) g_tokmap[off + s] = texts[bs * 128 + s];
}

// ---------------- 3xTF32 tensor-core GEMM ----------------
// C[packed_rows][1024] = A[rows][256] @ [Wf|Wb]^T + (b1+b2)
// GATHER=1: A row = emb[tokmap[row]]; GATHER=0: A row = A[row].
#define SMEM_G ((2 * 128 * 40 + 16 * 136) * 4)

template<int GATHER>
__global__ __launch_bounds__(256, 2) void k_gemm_tf32(
    const float* __restrict__ A,
    const float* __restrict__ Wf, const float* __restrict__ Wb,
    const float* __restrict__ b1f, const float* __restrict__ b2f,
    const float* __restrict__ b1b, const float* __restrict__ b2b,
    float* __restrict__ C)
{
    int total = g_segoff[256];
    int bm = blockIdx.x * 128;
    if (bm >= total) return;
    int bn = blockIdx.y * 128;
    const float *W, *bb1, *bb2; int nbase;
    if (bn < 512) { W = Wf; bb1 = b1f; bb2 = b2f; nbase = bn; }
    else          { W = Wb; bb1 = b1b; bb2 = b2b; nbase = bn - 512; }

    extern __shared__ float sm[];
    float* As     = sm;                   // [128][40]
    float* Bs     = sm + 128 * 40;        // [128][40]
    float* bias_s = sm + 2 * 128 * 40;    // [16][136]

    int tid = threadIdx.x;
    for (int i = tid; i < 16 * 128; i += 256) {
        int r = i >> 7, c = i & 127;
        bias_s[r * 136 + c] = bb1[nbase + c] + bb2[nbase + c];
    }

    int r0 = tid >> 3;
    int f4 = (tid & 7) * 4;
    const float* arow[4];
#pragma unroll
    for (int p = 0; p < 4; p++) {
        int pr = bm + r0 + 32 * p;
        if (GATHER) {
            int tok = (pr < total) ? g_tokmap[pr] : 0;
            arow[p] = A + (size_t)tok * 256;
        } else {
            arow[p] = A + (size_t)pr * 256;
        }
    }
    const float* wrow = W + (size_t)(nbase + r0) * 256;

    int wid = tid >> 5;
    int lm = (wid & 3) * 32;     // warp m offset (2 x m16)
    int ln = (wid >> 2) * 64;    // warp n offset (4 x n16)

    wmma::fragment<wmma::accumulator, 16, 16, 8, float> acc[2][4];
    __syncthreads();
#pragma unroll
    for (int mi = 0; mi < 2; mi++)
#pragma unroll
        for (int ni = 0; ni < 4; ni++)
            wmma::load_matrix_sync(acc[mi][ni], bias_s + ln + ni * 16, 136,
                                   wmma::mem_row_major);

    for (int k0 = 0; k0 < 256; k0 += 32) {
        float4 av[4], wv[4];
#pragma unroll
        for (int p = 0; p < 4; p++) {
            av[p] = *(const float4*)(arow[p] + k0 + f4);
            wv[p] = *(const float4*)(wrow + (size_t)p * 32 * 256 + k0 + f4);
        }
        __syncthreads();
#pragma unroll
        for (int p = 0; p < 4; p++) {
            *(float4*)&As[(r0 + 32 * p) * 40 + f4] = av[p];
            *(float4*)&Bs[(r0 + 32 * p) * 40 + f4] = wv[p];
        }
        __syncthreads();
#pragma unroll
        for (int ks = 0; ks < 4; ks++) {
            wmma::fragment<wmma::matrix_a, 16, 16, 8, wmma::precision::tf32,
                           wmma::row_major> ah[2], al[2];
#pragma unroll
            for (int mi = 0; mi < 2; mi++) {
                wmma::load_matrix_sync(ah[mi], As + (lm + mi * 16) * 40 + ks * 8, 40);
#pragma unroll
                for (int e = 0; e < ah[mi].num_elements; e++) {
                    float v = ah[mi].x[e];
                    float hi = wmma::__float_to_tf32(v);
                    ah[mi].x[e] = hi;
                    al[mi].x[e] = wmma::__float_to_tf32(v - hi);
                }
            }
#pragma unroll
            for (int ni = 0; ni < 4; ni++) {
                wmma::fragment<wmma::matrix_b, 16, 16, 8, wmma::precision::tf32,
                               wmma::col_major> bh, bl;
                wmma::load_matrix_sync(bh, Bs + (ln + ni * 16) * 40 + ks * 8, 40);
#pragma unroll
                for (int e = 0; e < bh.num_elements; e++) {
                    float v = bh.x[e];
                    float hi = wmma::__float_to_tf32(v);
                    bh.x[e] = hi;
                    bl.x[e] = wmma::__float_to_tf32(v - hi);
                }
#pragma unroll
                for (int mi = 0; mi < 2; mi++) {
                    wmma::mma_sync(acc[mi][ni], ah[mi], bl, acc[mi][ni]);
                    wmma::mma_sync(acc[mi][ni], al[mi], bh, acc[mi][ni]);
                    wmma::mma_sync(acc[mi][ni], ah[mi], bh, acc[mi][ni]);
                }
            }
        }
    }
#pragma unroll
    for (int mi = 0; mi < 2; mi++)
#pragma unroll
        for (int ni = 0; ni < 4; ni++)
            wmma::store_matrix_sync(
                C + (size_t)(bm + lm + mi * 16) * 1024 + bn + ln + ni * 16,
                acc[mi][ni], 1024, wmma::mem_row_major);
}

// ---------------- LSTM recurrent core ----------------
#define SMEM_LSTM ((512 * 68 + 128 + 512) * 4)

__device__ __forceinline__ void lstm_run(
    const float* __restrict__ Whh, const float* __restrict__ Gbase,
    float* __restrict__ Obase, int len, int dir, int t,
    float* ws, float* hs, float* ga,
    float h_init, float c_init, int write_final, int b)
{
    const float* wr = Whh + t * 128;
    float w[64];
#pragma unroll
    for (int q = 0; q < 16; q++) {
        float4 v = *(const float4*)(wr + q * 4);
        w[4*q]=v.x; w[4*q+1]=v.y; w[4*q+2]=v.z; w[4*q+3]=v.w;
    }
    float* wsr = ws + t * 68;
#pragma unroll
    for (int q = 0; q < 16; q++)
        *(float4*)(wsr + 4 * q) = *(const float4*)(wr + 64 + 4 * q);

    float c = c_init;
    if (t < 128) hs[t] = h_init;
    __syncthreads();

    int s    = dir ? (len - 1) : 0;
    int step = dir ? -1 : 1;
    float xg = Gbase[(size_t)s * 1024];
    for (int it = 0; it < len; it++) {
        int s_next = s + step;
        float xg_next = (it + 1 < len) ? Gbase[(size_t)s_next * 1024] : 0.0f;
        float acc = xg;
        const float4* h4 = (const float4*)hs;
#pragma unroll
        for (int q = 0; q < 16; q++) {
            float4 hv = h4[q];
            acc = fmaf(w[4*q  ], hv.x, acc);
            acc = fmaf(w[4*q+1], hv.y, acc);
            acc = fmaf(w[4*q+2], hv.z, acc);
            acc = fmaf(w[4*q+3], hv.w, acc);
        }
#pragma unroll
        for (int q = 0; q < 16; q++) {
            float4 wv = *(const float4*)(wsr + 4 * q);
            float4 hv = h4[16 + q];
            acc = fmaf(wv.x, hv.x, acc);
            acc = fmaf(wv.y, hv.y, acc);
            acc = fmaf(wv.z, hv.z, acc);
            acc = fmaf(wv.w, hv.w, acc);
        }
        float act;
        if ((t >> 7) == 2) act = tanhf(acc);
        else               act = 1.0f / (1.0f + expf(-acc));
        ga[t] = act;
        __syncthreads();
        if (t < 128) {
            float iv = ga[t], fv = ga[128 + t], gv = ga[256 + t], ov = ga[384 + t];
            c = fmaf(fv, c, iv * gv);
            float hn = ov * tanhf(c);
            hs[t] = hn;
            Obase[(size_t)s * 256 + t] = hn;
        }
        __syncthreads();
        xg = xg_next;
        s  = s_next;
    }
    if (write_final && t < 128) {
        g_Hf[dir][b][t] = hs[t];
        g_Cf[dir][b][t] = c;
    }
}

__global__ __launch_bounds__(512, 1) void k_lstm1(
    const int* __restrict__ lengths,
    const float* __restrict__ Whh_f, const float* __restrict__ Whh_b)
{
    extern __shared__ float sm[];
    float* ws = sm;
    float* hs = sm + 512 * 68;
    float* ga = hs + 128;
    int t   = threadIdx.x;
    int blk = blockIdx.x;
    int dir = blk >> 8;
    int b   = (blk & 255) >> 3;
    int seg = blk & 7;
    int bs  = b * NSEGC + seg;
    int len = lengths[bs];
    int off = g_segoff[bs];
    const float* Gbase = g_G1 + (size_t)off * 1024 + dir * 512 + t;
    float* Obase = g_P2 + (size_t)off * 256 + dir * 128;   // write packed directly
    lstm_run(dir ? Whh_b : Whh_f, Gbase, Obase, len, dir, t, ws, hs, ga,
             0.0f, 0.0f, (seg == NSEGC - 1), b);
}

__global__ __launch_bounds__(512, 1) void k_lstm2(
    const int* __restrict__ lengths,
    const float* __restrict__ Whh_f, const float* __restrict__ Whh_b)
{
    extern __shared__ float sm[];
    float* ws = sm;
    float* hs = sm + 512 * 68;
    float* ga = hs + 128;
    int t   = threadIdx.x;
    int blk = blockIdx.x;
    int dir = blk >> 5;
    int b   = blk & 31;
    int base = g_segoff[b * 8];
    int len  = g_segoff[b * 8 + 8] - base;
    float hi = (t < 128) ? g_Hf[dir][b][t & 127] : 0.0f;
    float ci = (t < 128) ? g_Cf[dir][b][t & 127] : 0.0f;
    const float* Gbase = g_G2 + (size_t)base * 1024 + dir * 512 + t;
    float* Obase = g_OUT2 + (size_t)base * 256 + dir * 128;
    lstm_run(dir ? Whh_b : Whh_f, Gbase, Obase, len, dir, t, ws, hs, ga,
             hi, ci, 0, b);
}

// ---------------- emission = OUT2 @ Wlin^T + blin (packed) ----------------
__global__ void k_emission(const float* __restrict__ Wlin, const float* __restrict__ blin)
{
    int b = blockIdx.x;
    int base = g_segoff[b * 8];
    int L    = g_segoff[b * 8 + 8] - base;
    for (int idx = threadIdx.x; idx < L * 16; idx += blockDim.x) {
        int t = idx >> 4, k = idx & 15;
        const float4* xr = (const float4*)(g_OUT2 + (size_t)(base + t) * 256);
        const float4* wr = (const float4*)(Wlin + k * 256);
        float a0 = 0.f;
#pragma unroll
        for (int q = 0; q < 64; q++) {
            float4 x = xr[q], w = wr[q];
            a0 = fmaf(x.x, w.x, a0); a0 = fmaf(x.y, w.y, a0);
            a0 = fmaf(x.z, w.z, a0); a0 = fmaf(x.w, w.w, a0);
        }
        g_EM[(size_t)(base + t) * 16 + k] = a0 + blin[k];
    }
}

// ---------------- Viterbi: warp per batch, K=16 in lanes ----------------
__global__ __launch_bounds__(1024, 1) void k_viterbi(
    const float* __restrict__ startv, const float* __restrict__ trans,
    const float* __restrict__ endv, float* __restrict__ out)
{
    int tid  = threadIdx.x;
    int b    = tid >> 5;
    int lane = tid & 31;
    int j    = lane & 15;
    int base = g_segoff[b * 8];
    int L    = g_segoff[b * 8 + 8] - base;
    float trC[16];
#pragma unroll
    for (int i = 0; i < 16; i++) trC[i] = trans[i * 16 + j];
    const float* em = g_EM + (size_t)base * 16;

    float sc  = startv[j] + em[j];
    float emj = em[16 + j];
    unsigned char* hist = (unsigned char*)g_HIST4;
    for (int t = 1; t < L; t++) {
        float em_next = (t + 1 < L) ? em[(t + 1) * 16 + j] : 0.0f;
        float best = -3.4e38f; int bi = 0;
#pragma unroll
        for (int i = 0; i < 16; i++) {
            float v = (__shfl_sync(0xFFFFFFFFu, sc, i) + trC[i]) + emj;
            if (v > best) { best = v; bi = i; }
        }
        sc = best;
        if (lane < 16)
            hist[((size_t)(t - 1) * 32 + b) * 16 + j] = (unsigned char)bi;
        emj = em_next;
    }
    float fin = sc + endv[j];
    float bestv = -3.4e38f; int last = 0;
#pragma unroll
    for (int i = 0; i < 16; i++) {
        float v = __shfl_sync(0xFFFFFFFFu, fin, i);
        if (v > bestv) { bestv = v; last = i; }
    }
    if (lane == 0) {
        out[32768 + b] = bestv;
        int cur = last;
        out[(TTOT - 1) * 32 + b] = (float)cur;
#pragma unroll 4
        for (int t = TTOT - 1; t >= 1; t--) {
            uint4 hrow = g_HIST4[(size_t)(t - 1) * 32 + b];
            if (t < L) {
                unsigned wv = ((const unsigned*)&hrow)[cur >> 2];
                cur = (int)((wv >> ((cur & 3) * 8)) & 0xFFu);
            }
            out[(t - 1) * 32 + b] = (float)cur;
        }
    }
}

// ---------------- launch ----------------
extern "C" void kernel_launch(void* const* d_in, const int* in_sizes, int n_in,
                              void* d_out, int out_size)
{
    const int*   texts   = (const int*)  d_in[0];
    const int*   lengths = (const int*)  d_in[1];
    const float* emb     = (const float*)d_in[2];
    const float* Wih_f   = (const float*)d_in[3];
    const float* Whh_f   = (const float*)d_in[4];
    const float* bih_f   = (const float*)d_in[5];
    const float* bhh_f   = (const float*)d_in[6];
    const float* Wih_b   = (const float*)d_in[7];
    const float* Whh_b   = (const float*)d_in[8];
    const float* bih_b   = (const float*)d_in[9];
    const float* bhh_b   = (const float*)d_in[10];
    const float* Wlin    = (const float*)d_in[11];
    const float* blin    = (const float*)d_in[12];
    const float* crf_s   = (const float*)d_in[13];
    const float* crf_t   = (const float*)d_in[14];
    const float* crf_e   = (const float*)d_in[15];
    float* out = (float*)d_out;

    cudaFuncSetAttribute(k_lstm1, cudaFuncAttributeMaxDynamicSharedMemorySize, SMEM_LSTM);
    cudaFuncSetAttribute(k_lstm2, cudaFuncAttributeMaxDynamicSharedMemorySize, SMEM_LSTM);
    cudaFuncSetAttribute(k_gemm_tf32<1>, cudaFuncAttributeMaxDynamicSharedMemorySize, SMEM_G);
    cudaFuncSetAttribute(k_gemm_tf32<0>, cudaFuncAttributeMaxDynamicSharedMemorySize, SMEM_G);

    float *pG1, *pP2, *pG2;
    cudaGetSymbolAddress((void**)&pG1, g_G1);
    cudaGetSymbolAddress((void**)&pP2, g_P2);
    cudaGetSymbolAddress((void**)&pG2, g_G2);

    k_offsets<<<1, 32>>>(lengths);
    k_rowmap<<<256, 128>>>(texts, lengths);
    k_gemm_tf32<1><<<dim3(256, 8), 256, SMEM_G>>>(emb, Wih_f, Wih_b,
                                                  bih_f, bhh_f, bih_b, bhh_b, pG1);
    k_lstm1<<<512, 512, SMEM_LSTM>>>(lengths, Whh_f, Whh_b);
    k_gemm_tf32<0><<<dim3(256, 8), 256, SMEM_G>>>(pP2, Wih_f, Wih_b,
                                                  bih_f, bhh_f, bih_b, bhh_b, pG2);
    k_lstm2<<<64, 512, SMEM_LSTM>>>(lengths, Whh_f, Whh_b);
    k_emission<<<32, 256>>>(Wlin, blin);
    k_viterbi<<<1, 1024>>>(crf_s, crf_t, crf_e, out);
}